// round 1
// baseline (speedup 1.0000x reference)
#include <cuda_runtime.h>
#include <math.h>

// SparseDimAttention, GB300 sm_103a.
// One CTA per batch. Phases:
//  1) scores[d] = sum_l v[l]*x[b,l,d] + c   (v = ws @ Wp, c = ws@bp + bs)  -- single DRAM pass over x
//  2) block max
//  3) radix-select threshold for exact top-K (tie-break: lowest index, matching jax.lax.top_k)
//  4) softmax weights written in-place over scores in SMEM
//  5) y[l] = (sum_d w[d]*x[b,l,d]) / Z      -- re-read of x[b] expected to hit L2 (1 CTA/SM forced)
//  6) head: out = Wp@y+bp -> LayerNorm -> W1+GELU(exact) -> W2

#define NT 512
constexpr int Ll = 33, Dd = 4096, Pp = 64, Kk = 512, Hh = 128;
constexpr int CHUNK = Dd / NT; // 8
// pad dynamic smem to force 1 CTA/SM (L2 working-set control): 2*132KB > 228KB carveout
constexpr int SMEM_BYTES = 132 * 1024;

__device__ __forceinline__ unsigned int fkey(float f) {
    unsigned int u = __float_as_uint(f);
    return u ^ ((u & 0x80000000u) ? 0xFFFFFFFFu : 0x80000000u); // ascending monotonic
}

__global__ void __launch_bounds__(NT, 1) sda_kernel(
    const float* __restrict__ x, const float* __restrict__ Wp,
    const float* __restrict__ bp, const float* __restrict__ ws,
    const float* __restrict__ bsc, const float* __restrict__ gamma,
    const float* __restrict__ beta, const float* __restrict__ W1,
    const float* __restrict__ b1, const float* __restrict__ W2,
    const float* __restrict__ b2, float* __restrict__ out)
{
    extern __shared__ float sc[]; // [Dd] scores, later softmax weights (rest is padding)
    __shared__ float v[Ll];
    __shared__ float yv[Ll];
    __shared__ float red[16];
    __shared__ unsigned int hist[256];
    __shared__ int scanbuf[NT];
    __shared__ float zs[Pp];
    __shared__ float as_[Hh];
    __shared__ float s_c, s_m, s_invZ, s_mu, s_rstd;
    __shared__ unsigned int s_prefix, s_mask;
    __shared__ int s_need;

    const int b = blockIdx.x;
    const int tid = threadIdx.x;
    const int lane = tid & 31, wid = tid >> 5;
    const float* __restrict__ xb = x + (size_t)b * (Ll * Dd);

    // ---- phase 0: fold score projection: v[l] = sum_p ws[p]*Wp[p,l]; c = ws@bp + bs ----
    if (tid < Ll) {
        float acc = 0.f;
        #pragma unroll
        for (int p = 0; p < Pp; ++p) acc = fmaf(ws[p], Wp[p * Ll + tid], acc);
        v[tid] = acc;
    } else if (tid == Ll) {
        float acc = bsc[0];
        #pragma unroll
        for (int p = 0; p < Pp; ++p) acc = fmaf(ws[p], bp[p], acc);
        s_c = acc;
    } else if (tid == Ll + 1) {
        s_prefix = 0u; s_mask = 0u; s_need = Kk;
    }
    __syncthreads();

    // ---- phase 1: scores (float4 streaming) ----
    {
        float vr[Ll];
        #pragma unroll
        for (int l = 0; l < Ll; ++l) vr[l] = v[l];
        const float cc = s_c;
        const float4* __restrict__ xb4 = reinterpret_cast<const float4*>(xb);
        float4* sc4 = reinterpret_cast<float4*>(sc);
        #pragma unroll
        for (int it = 0; it < Dd / (4 * NT); ++it) {  // 2 iterations
            const int d4 = it * NT + tid;
            float4 acc = make_float4(cc, cc, cc, cc);
            #pragma unroll
            for (int l = 0; l < Ll; ++l) {
                float4 xv = xb4[(size_t)l * (Dd / 4) + d4];
                acc.x = fmaf(vr[l], xv.x, acc.x);
                acc.y = fmaf(vr[l], xv.y, acc.y);
                acc.z = fmaf(vr[l], xv.z, acc.z);
                acc.w = fmaf(vr[l], xv.w, acc.w);
            }
            sc4[d4] = acc;
        }
    }
    __syncthreads();

    // ---- phase 2: block max (top-1 is always selected, so this is the softmax max) ----
    {
        float m = -INFINITY;
        #pragma unroll
        for (int it = 0; it < CHUNK; ++it) m = fmaxf(m, sc[it * NT + tid]);
        #pragma unroll
        for (int o = 16; o > 0; o >>= 1) m = fmaxf(m, __shfl_xor_sync(0xFFFFFFFFu, m, o));
        if (lane == 0) red[wid] = m;
        __syncthreads();
        if (tid < 16) {
            m = red[tid];
            #pragma unroll
            for (int o = 8; o > 0; o >>= 1) m = fmaxf(m, __shfl_xor_sync(0x0000FFFFu, m, o));
            if (tid == 0) s_m = m;
        }
    }
    __syncthreads();

    // ---- phase 3: 4x8-bit MSB radix select: threshold key T, rem = #ties to take ----
    for (int shift = 24; shift >= 0; shift -= 8) {
        if (tid < 256) hist[tid] = 0u;
        __syncthreads();
        const unsigned int pfx = s_prefix, msk = s_mask;
        #pragma unroll
        for (int it = 0; it < CHUNK; ++it) {
            unsigned int k = fkey(sc[it * NT + tid]);
            if ((k & msk) == pfx) atomicAdd(&hist[(k >> shift) & 0xFFu], 1u);
        }
        __syncthreads();
        if (tid == 0) {
            int need = s_need, cum = 0, vd = 0;
            for (int vv = 255; vv >= 0; --vv) {
                int h = (int)hist[vv];
                if (cum + h >= need) { vd = vv; break; }
                cum += h;
            }
            s_need = need - cum;
            s_prefix |= ((unsigned int)vd) << shift;
            s_mask |= (0xFFu << shift);
        }
        __syncthreads();
    }

    // ---- phase 4: selection (index-ordered ties) + exp weights in place + Z ----
    {
        const unsigned int T = s_prefix;
        const int rem = s_need;
        const float mmax = s_m;
        const int base = tid * CHUNK;
        int cnt = 0;
        #pragma unroll
        for (int j = 0; j < CHUNK; ++j) cnt += (fkey(sc[base + j]) == T);
        scanbuf[tid] = cnt;
        __syncthreads();
        if (tid == 0) {  // exclusive scan (512 elems, negligible)
            int run = 0;
            for (int i = 0; i < NT; ++i) { int t = scanbuf[i]; scanbuf[i] = run; run += t; }
        }
        __syncthreads();
        int run = scanbuf[tid];
        float zp = 0.f;
        #pragma unroll
        for (int j = 0; j < CHUNK; ++j) {
            float s = sc[base + j];
            unsigned int k = fkey(s);
            bool sel;
            if (k > T)       sel = true;
            else if (k == T) { sel = (run < rem); ++run; }
            else             sel = false;
            float w = sel ? expf(s - mmax) : 0.f;
            sc[base + j] = w;
            zp += w;
        }
        #pragma unroll
        for (int o = 16; o > 0; o >>= 1) zp += __shfl_xor_sync(0xFFFFFFFFu, zp, o);
        if (lane == 0) red[wid] = zp;
        __syncthreads();
        if (tid < 16) {
            zp = red[tid];
            #pragma unroll
            for (int o = 8; o > 0; o >>= 1) zp += __shfl_xor_sync(0x0000FFFFu, zp, o);
            if (tid == 0) s_invZ = 1.f / zp;
        }
    }
    __syncthreads();

    // ---- phase 5: y[l] = invZ * sum_d w[d]*x[b,l,d]  (x[b] re-read: L2 hit) ----
    {
        const float invZ = s_invZ;
        const float4* sc4 = reinterpret_cast<const float4*>(sc);
        for (int l = wid; l < Ll; l += 16) {
            const float4* __restrict__ xr4 = reinterpret_cast<const float4*>(xb + (size_t)l * Dd);
            float a0 = 0.f, a1 = 0.f, a2 = 0.f, a3 = 0.f;
            #pragma unroll 4
            for (int i = lane; i < Dd / 4; i += 32) {
                float4 wv = sc4[i];
                float4 xv = xr4[i];
                a0 = fmaf(wv.x, xv.x, a0);
                a1 = fmaf(wv.y, xv.y, a1);
                a2 = fmaf(wv.z, xv.z, a2);
                a3 = fmaf(wv.w, xv.w, a3);
            }
            float acc = (a0 + a1) + (a2 + a3);
            #pragma unroll
            for (int o = 16; o > 0; o >>= 1) acc += __shfl_xor_sync(0xFFFFFFFFu, acc, o);
            if (lane == 0) yv[l] = acc * invZ;
        }
    }
    __syncthreads();

    // ---- phase 6: head ----
    if (tid < Pp) {
        float acc = bp[tid];
        #pragma unroll
        for (int l = 0; l < Ll; ++l) acc = fmaf(Wp[tid * Ll + l], yv[l], acc);
        zs[tid] = acc;
    }
    __syncthreads();
    if (tid < 32) {  // LayerNorm stats over 64 (2 per lane)
        float a = zs[tid], bq = zs[tid + 32];
        float sum = a + bq;
        #pragma unroll
        for (int o = 16; o > 0; o >>= 1) sum += __shfl_xor_sync(0xFFFFFFFFu, sum, o);
        float mu = sum * (1.f / 64.f);
        float da = a - mu, db = bq - mu;
        float sq = da * da + db * db;
        #pragma unroll
        for (int o = 16; o > 0; o >>= 1) sq += __shfl_xor_sync(0xFFFFFFFFu, sq, o);
        if (tid == 0) { s_mu = mu; s_rstd = rsqrtf(sq * (1.f / 64.f) + 1e-5f); }
    }
    __syncthreads();
    if (tid < Pp) zs[tid] = (zs[tid] - s_mu) * s_rstd * gamma[tid] + beta[tid];
    __syncthreads();
    if (tid < Hh) {
        float acc = b1[tid];
        #pragma unroll
        for (int p = 0; p < Pp; ++p) acc = fmaf(W1[tid * Pp + p], zs[p], acc);
        as_[tid] = 0.5f * acc * (1.f + erff(acc * 0.70710678118654752f)); // exact GELU
    }
    __syncthreads();
    if (tid < 2) {
        float acc = b2[tid];
        #pragma unroll
        for (int h = 0; h < Hh; ++h) acc = fmaf(W2[tid * Hh + h], as_[h], acc);
        out[b * 2 + tid] = acc;
    }
}

extern "C" void kernel_launch(void* const* d_in, const int* in_sizes, int n_in,
                              void* d_out, int out_size) {
    const float* x     = (const float*)d_in[0];
    const float* Wp    = (const float*)d_in[1];
    const float* bp    = (const float*)d_in[2];
    const float* ws    = (const float*)d_in[3];
    const float* bsc   = (const float*)d_in[4];
    const float* gamma = (const float*)d_in[5];
    const float* beta  = (const float*)d_in[6];
    const float* W1    = (const float*)d_in[7];
    const float* b1    = (const float*)d_in[8];
    const float* W2    = (const float*)d_in[9];
    const float* b2    = (const float*)d_in[10];
    float* out = (float*)d_out;

    cudaFuncSetAttribute(sda_kernel, cudaFuncAttributeMaxDynamicSharedMemorySize, SMEM_BYTES);
    sda_kernel<<<512, NT, SMEM_BYTES>>>(x, Wp, bp, ws, bsc, gamma, beta, W1, b1, W2, b2, out);
}

// round 2
// speedup vs baseline: 1.1109x; 1.1109x over previous
#include <cuda_runtime.h>
#include <math.h>

// SparseDimAttention, GB300 sm_103a — two-kernel split for full memory overlap.
// K1: scores[b,d] = sum_l v[l]*x[b,l,d] + c (v = ws@Wp, c = ws@bp+bs). Full-occupancy stream.
// K2: per-batch top-K radix select + softmax + weighted re-read of x + tiny head.

constexpr int Ll = 33, Dd = 4096, Pp = 64, Kk = 512, Hh = 128, Bb = 512;

__device__ float g_scores[(size_t)Bb * Dd];  // 8 MB scratch (allowed: __device__ global)

__device__ __forceinline__ unsigned int fkey(float f) {
    unsigned int u = __float_as_uint(f);
    return u ^ ((u & 0x80000000u) ? 0xFFFFFFFFu : 0x80000000u); // ascending monotonic
}

// ---------------- Kernel 1: scores ----------------
__global__ void __launch_bounds__(256) scores_kernel(
    const float* __restrict__ x, const float* __restrict__ Wp,
    const float* __restrict__ bp, const float* __restrict__ ws,
    const float* __restrict__ bsc)
{
    __shared__ float v[Ll];
    __shared__ float s_c;
    const int tid = threadIdx.x;
    if (tid < Ll) {
        float a = 0.f;
        #pragma unroll
        for (int p = 0; p < Pp; ++p) a = fmaf(ws[p], Wp[p * Ll + tid], a);
        v[tid] = a;
    } else if (tid == Ll) {
        float a = bsc[0];
        #pragma unroll
        for (int p = 0; p < Pp; ++p) a = fmaf(ws[p], bp[p], a);
        s_c = a;
    }
    __syncthreads();

    const int b  = blockIdx.x >> 2;               // 4 CTAs per batch
    const int d4 = ((blockIdx.x & 3) << 8) + tid; // 0..1023 (float4 granularity)
    const float4* __restrict__ xb4 =
        reinterpret_cast<const float4*>(x) + (size_t)b * Ll * (Dd / 4) + d4;
    const float c = s_c;
    float4 acc = make_float4(c, c, c, c);
    #pragma unroll
    for (int l = 0; l < Ll; ++l) {
        float4 xv = xb4[(size_t)l * (Dd / 4)];
        const float vl = v[l];
        acc.x = fmaf(vl, xv.x, acc.x);
        acc.y = fmaf(vl, xv.y, acc.y);
        acc.z = fmaf(vl, xv.z, acc.z);
        acc.w = fmaf(vl, xv.w, acc.w);
    }
    reinterpret_cast<float4*>(g_scores)[(size_t)b * (Dd / 4) + d4] = acc;
}

// ---------------- Kernel 2: top-k + softmax + weighted sum + head ----------------
#define NTB 512
constexpr int CH = Dd / NTB; // 8

__global__ void __launch_bounds__(NTB, 2) topk_kernel(
    const float* __restrict__ x, const float* __restrict__ Wp,
    const float* __restrict__ bp, const float* __restrict__ gamma,
    const float* __restrict__ beta, const float* __restrict__ W1,
    const float* __restrict__ b1, const float* __restrict__ W2,
    const float* __restrict__ b2, float* __restrict__ out)
{
    __shared__ float sc[Dd];      // scores -> softmax weights (16 KB)
    __shared__ int   hist[256];
    __shared__ float red[16];
    __shared__ int   warpsum[16];
    __shared__ float yv[Ll];
    __shared__ float zs[Pp];
    __shared__ float as_[Hh];
    __shared__ float s_m, s_invZ, s_mu, s_rstd;
    __shared__ unsigned int s_prefix;
    __shared__ int s_need;

    const int b = blockIdx.x;
    const int tid = threadIdx.x;
    const int lane = tid & 31, wid = tid >> 5;
    const float* __restrict__ xb = x + (size_t)b * (Ll * Dd);

    // ---- load scores + block max ----
    float m = -INFINITY;
    #pragma unroll
    for (int it = 0; it < CH; ++it) {
        float s = g_scores[(size_t)b * Dd + it * NTB + tid];
        sc[it * NTB + tid] = s;
        m = fmaxf(m, s);
    }
    #pragma unroll
    for (int o = 16; o > 0; o >>= 1) m = fmaxf(m, __shfl_xor_sync(0xFFFFFFFFu, m, o));
    if (lane == 0) red[wid] = m;
    if (tid == 0) { s_prefix = 0u; s_need = Kk; }
    __syncthreads();
    if (tid < 16) {
        m = red[tid];
        #pragma unroll
        for (int o = 8; o > 0; o >>= 1) m = fmaxf(m, __shfl_xor_sync(0x0000FFFFu, m, o));
        if (tid == 0) s_m = m;
    }
    __syncthreads();

    // ---- 4x8-bit MSB radix select (parallel bin suffix-scan) ----
    #pragma unroll
    for (int shift = 24; shift >= 0; shift -= 8) {
        const unsigned int msk = (shift == 24) ? 0u : (0xFFFFFFFFu << (shift + 8));
        if (tid < 256) hist[tid] = 0;
        __syncthreads();
        const unsigned int pfx = s_prefix;
        #pragma unroll
        for (int it = 0; it < CH; ++it) {
            unsigned int k = fkey(sc[it * NTB + tid]);
            if ((k & msk) == (pfx & msk)) atomicAdd(&hist[(k >> shift) & 0xFFu], 1);
        }
        __syncthreads();
        // inclusive suffix scan: hist[i] = #keys with bin >= i (within prefix)
        #pragma unroll
        for (int off = 1; off < 256; off <<= 1) {
            int t = 0;
            if (tid < 256 && tid + off < 256) t = hist[tid + off];
            __syncthreads();
            if (tid < 256) hist[tid] += t;
            __syncthreads();
        }
        const int need = s_need;
        __syncthreads();
        if (tid < 256) {
            const int sv  = hist[tid];
            const int sv1 = (tid < 255) ? hist[tid + 1] : 0;
            if (sv >= need && sv1 < need) {  // unique bin
                s_prefix = pfx | ((unsigned int)tid << shift);
                s_need = need - sv1;
            }
        }
        __syncthreads();
    }

    // ---- selection (index-ordered ties) + exp weights in place + Z ----
    {
        const unsigned int T = s_prefix;
        const int rem = s_need;
        const float mmax = s_m;
        const int base = tid * CH;
        int cnt = 0;
        #pragma unroll
        for (int j = 0; j < CH; ++j) cnt += (fkey(sc[base + j]) == T);
        // exclusive scan of 512 tie-counts via warp shuffles
        int inc = cnt;
        #pragma unroll
        for (int o = 1; o < 32; o <<= 1) {
            int t = __shfl_up_sync(0xFFFFFFFFu, inc, o);
            if (lane >= o) inc += t;
        }
        if (lane == 31) warpsum[wid] = inc;
        __syncthreads();
        if (tid < 16) {
            int w = warpsum[tid];
            int iw = w;
            #pragma unroll
            for (int o = 1; o < 16; o <<= 1) {
                int t = __shfl_up_sync(0x0000FFFFu, iw, o);
                if (tid >= o) iw += t;
            }
            warpsum[tid] = iw - w;  // exclusive
        }
        __syncthreads();
        int run = warpsum[wid] + (inc - cnt);

        float zp = 0.f;
        #pragma unroll
        for (int j = 0; j < CH; ++j) {
            float s = sc[base + j];
            unsigned int k = fkey(s);
            bool sel;
            if (k > T)       sel = true;
            else if (k == T) { sel = (run < rem); ++run; }
            else             sel = false;
            float w = sel ? expf(s - mmax) : 0.f;
            sc[base + j] = w;
            zp += w;
        }
        #pragma unroll
        for (int o = 16; o > 0; o >>= 1) zp += __shfl_xor_sync(0xFFFFFFFFu, zp, o);
        if (lane == 0) red[wid] = zp;
        __syncthreads();
        if (tid < 16) {
            zp = red[tid];
            #pragma unroll
            for (int o = 8; o > 0; o >>= 1) zp += __shfl_xor_sync(0x0000FFFFu, zp, o);
            if (tid == 0) s_invZ = 1.f / zp;
        }
    }
    __syncthreads();

    // ---- weighted sum: y[l] = invZ * sum_d w[d]*x[b,l,d]  (dense DRAM stream) ----
    {
        const float invZ = s_invZ;
        const float4* sc4 = reinterpret_cast<const float4*>(sc);
        for (int l = wid; l < Ll; l += 16) {
            const float4* __restrict__ xr4 = reinterpret_cast<const float4*>(xb + (size_t)l * Dd);
            float a0 = 0.f, a1 = 0.f, a2 = 0.f, a3 = 0.f;
            #pragma unroll 4
            for (int i = lane; i < Dd / 4; i += 32) {
                float4 wv = sc4[i];
                float4 xv = xr4[i];
                a0 = fmaf(wv.x, xv.x, a0);
                a1 = fmaf(wv.y, xv.y, a1);
                a2 = fmaf(wv.z, xv.z, a2);
                a3 = fmaf(wv.w, xv.w, a3);
            }
            float acc = (a0 + a1) + (a2 + a3);
            #pragma unroll
            for (int o = 16; o > 0; o >>= 1) acc += __shfl_xor_sync(0xFFFFFFFFu, acc, o);
            if (lane == 0) yv[l] = acc * invZ;
        }
    }
    __syncthreads();

    // ---- head: Wp@y+bp -> LayerNorm -> W1+GELU(exact) -> W2 ----
    if (tid < Pp) {
        float acc = bp[tid];
        #pragma unroll
        for (int l = 0; l < Ll; ++l) acc = fmaf(Wp[tid * Ll + l], yv[l], acc);
        zs[tid] = acc;
    }
    __syncthreads();
    if (tid < 32) {
        float a = zs[tid], bq = zs[tid + 32];
        float sum = a + bq;
        #pragma unroll
        for (int o = 16; o > 0; o >>= 1) sum += __shfl_xor_sync(0xFFFFFFFFu, sum, o);
        float mu = sum * (1.f / 64.f);
        float da = a - mu, db = bq - mu;
        float sq = da * da + db * db;
        #pragma unroll
        for (int o = 16; o > 0; o >>= 1) sq += __shfl_xor_sync(0xFFFFFFFFu, sq, o);
        if (tid == 0) { s_mu = mu; s_rstd = rsqrtf(sq * (1.f / 64.f) + 1e-5f); }
    }
    __syncthreads();
    if (tid < Pp) zs[tid] = (zs[tid] - s_mu) * s_rstd * gamma[tid] + beta[tid];
    __syncthreads();
    if (tid < Hh) {
        float acc = b1[tid];
        #pragma unroll
        for (int p = 0; p < Pp; ++p) acc = fmaf(W1[tid * Pp + p], zs[p], acc);
        as_[tid] = 0.5f * acc * (1.f + erff(acc * 0.70710678118654752f)); // exact GELU
    }
    __syncthreads();
    if (tid < 2) {
        float acc = b2[tid];
        #pragma unroll
        for (int h = 0; h < Hh; ++h) acc = fmaf(W2[tid * Hh + h], as_[h], acc);
        out[b * 2 + tid] = acc;
    }
}

extern "C" void kernel_launch(void* const* d_in, const int* in_sizes, int n_in,
                              void* d_out, int out_size) {
    const float* x     = (const float*)d_in[0];
    const float* Wp    = (const float*)d_in[1];
    const float* bp    = (const float*)d_in[2];
    const float* ws    = (const float*)d_in[3];
    const float* bsc   = (const float*)d_in[4];
    const float* gamma = (const float*)d_in[5];
    const float* beta  = (const float*)d_in[6];
    const float* W1    = (const float*)d_in[7];
    const float* b1    = (const float*)d_in[8];
    const float* W2    = (const float*)d_in[9];
    const float* b2    = (const float*)d_in[10];
    float* out = (float*)d_out;

    scores_kernel<<<Bb * 4, 256>>>(x, Wp, bp, ws, bsc);
    topk_kernel<<<Bb, NTB>>>(x, Wp, bp, gamma, beta, W1, b1, W2, b2, out);
}

// round 3
// speedup vs baseline: 1.1264x; 1.0139x over previous
#include <cuda_runtime.h>
#include <math.h>

// SparseDimAttention, GB300 sm_103a — 4-kernel pipeline, streaming fully decoupled.
// K1: scores[b,d] = sum_l v[l]*x[b,l,d] + c       (276 MB stream @ ~6.2 TB/s)
// K2: per-batch exact top-K radix select + softmax -> normalized weights w[b,d]
// K3: y[b,l] = sum_d w[b,d]*x[b,l,d]              (276 MB stream @ ~6.2 TB/s)
// K4: head: Wp@y+bp -> LayerNorm -> W1+GELU -> W2

constexpr int Ll = 33, Dd = 4096, Pp = 64, Kk = 512, Hh = 128, Bb = 512;

__device__ float g_scores[(size_t)Bb * Dd];  // 8 MB
__device__ float g_w[(size_t)Bb * Dd];       // 8 MB normalized softmax weights
__device__ float g_y[(size_t)Bb * Ll];

__device__ __forceinline__ unsigned int fkey(float f) {
    unsigned int u = __float_as_uint(f);
    return u ^ ((u & 0x80000000u) ? 0xFFFFFFFFu : 0x80000000u); // ascending monotonic
}

// ---------------- K1: scores ----------------
__global__ void __launch_bounds__(256) scores_kernel(
    const float* __restrict__ x, const float* __restrict__ Wp,
    const float* __restrict__ bp, const float* __restrict__ ws,
    const float* __restrict__ bsc)
{
    __shared__ float v[Ll];
    __shared__ float s_c;
    const int tid = threadIdx.x;
    if (tid < Ll) {
        float a = 0.f;
        #pragma unroll
        for (int p = 0; p < Pp; ++p) a = fmaf(ws[p], Wp[p * Ll + tid], a);
        v[tid] = a;
    } else if (tid == Ll) {
        float a = bsc[0];
        #pragma unroll
        for (int p = 0; p < Pp; ++p) a = fmaf(ws[p], bp[p], a);
        s_c = a;
    }
    __syncthreads();

    const int b  = blockIdx.x >> 2;
    const int d4 = ((blockIdx.x & 3) << 8) + tid;
    const float4* __restrict__ xb4 =
        reinterpret_cast<const float4*>(x) + (size_t)b * Ll * (Dd / 4) + d4;
    const float c = s_c;
    float4 acc = make_float4(c, c, c, c);
    #pragma unroll
    for (int l = 0; l < Ll; ++l) {
        float4 xv = xb4[(size_t)l * (Dd / 4)];
        const float vl = v[l];
        acc.x = fmaf(vl, xv.x, acc.x);
        acc.y = fmaf(vl, xv.y, acc.y);
        acc.z = fmaf(vl, xv.z, acc.z);
        acc.w = fmaf(vl, xv.w, acc.w);
    }
    reinterpret_cast<float4*>(g_scores)[(size_t)b * (Dd / 4) + d4] = acc;
}

// ---------------- K2: top-k + softmax -> w ----------------
#define NTB 512
constexpr int CH = Dd / NTB; // 8

__global__ void __launch_bounds__(NTB) topk_w_kernel()
{
    __shared__ float sc[Dd];      // 16 KB
    __shared__ int   hist[256];
    __shared__ float red[16];
    __shared__ int   warpsum[16];
    __shared__ float s_m, s_invZ;
    __shared__ unsigned int s_prefix;
    __shared__ int s_need;

    const int b = blockIdx.x;
    const int tid = threadIdx.x;
    const int lane = tid & 31, wid = tid >> 5;

    // load scores + block max
    float m = -INFINITY;
    #pragma unroll
    for (int it = 0; it < CH; ++it) {
        float s = g_scores[(size_t)b * Dd + it * NTB + tid];
        sc[it * NTB + tid] = s;
        m = fmaxf(m, s);
    }
    #pragma unroll
    for (int o = 16; o > 0; o >>= 1) m = fmaxf(m, __shfl_xor_sync(0xFFFFFFFFu, m, o));
    if (lane == 0) red[wid] = m;
    if (tid == 0) { s_prefix = 0u; s_need = Kk; }
    __syncthreads();
    if (tid < 16) {
        m = red[tid];
        #pragma unroll
        for (int o = 8; o > 0; o >>= 1) m = fmaxf(m, __shfl_xor_sync(0x0000FFFFu, m, o));
        if (tid == 0) s_m = m;
    }
    __syncthreads();

    // 4x8-bit MSB radix select
    #pragma unroll
    for (int shift = 24; shift >= 0; shift -= 8) {
        const unsigned int msk = (shift == 24) ? 0u : (0xFFFFFFFFu << (shift + 8));
        if (tid < 256) hist[tid] = 0;
        __syncthreads();
        const unsigned int pfx = s_prefix;
        #pragma unroll
        for (int it = 0; it < CH; ++it) {
            unsigned int k = fkey(sc[it * NTB + tid]);
            if ((k & msk) == (pfx & msk)) atomicAdd(&hist[(k >> shift) & 0xFFu], 1);
        }
        __syncthreads();
        #pragma unroll
        for (int off = 1; off < 256; off <<= 1) {  // inclusive suffix scan over bins
            int t = 0;
            if (tid < 256 && tid + off < 256) t = hist[tid + off];
            __syncthreads();
            if (tid < 256) hist[tid] += t;
            __syncthreads();
        }
        const int need = s_need;
        __syncthreads();
        if (tid < 256) {
            const int sv  = hist[tid];
            const int sv1 = (tid < 255) ? hist[tid + 1] : 0;
            if (sv >= need && sv1 < need) {
                s_prefix = pfx | ((unsigned int)tid << shift);
                s_need = need - sv1;
            }
        }
        __syncthreads();
    }

    // selection (index-ordered ties) + exp weights + Z
    const unsigned int T = s_prefix;
    const int rem = s_need;
    const float mmax = s_m;
    const int base = tid * CH;
    int cnt = 0;
    #pragma unroll
    for (int j = 0; j < CH; ++j) cnt += (fkey(sc[base + j]) == T);
    int inc = cnt;
    #pragma unroll
    for (int o = 1; o < 32; o <<= 1) {
        int t = __shfl_up_sync(0xFFFFFFFFu, inc, o);
        if (lane >= o) inc += t;
    }
    if (lane == 31) warpsum[wid] = inc;
    __syncthreads();
    if (tid < 16) {
        int w = warpsum[tid];
        int iw = w;
        #pragma unroll
        for (int o = 1; o < 16; o <<= 1) {
            int t = __shfl_up_sync(0x0000FFFFu, iw, o);
            if (tid >= o) iw += t;
        }
        warpsum[tid] = iw - w;
    }
    __syncthreads();
    int run = warpsum[wid] + (inc - cnt);

    float zp = 0.f;
    #pragma unroll
    for (int j = 0; j < CH; ++j) {
        float s = sc[base + j];
        unsigned int k = fkey(s);
        bool sel;
        if (k > T)       sel = true;
        else if (k == T) { sel = (run < rem); ++run; }
        else             sel = false;
        float w = sel ? expf(s - mmax) : 0.f;
        sc[base + j] = w;
        zp += w;
    }
    #pragma unroll
    for (int o = 16; o > 0; o >>= 1) zp += __shfl_xor_sync(0xFFFFFFFFu, zp, o);
    if (lane == 0) red[wid] = zp;
    __syncthreads();
    if (tid < 16) {
        zp = red[tid];
        #pragma unroll
        for (int o = 8; o > 0; o >>= 1) zp += __shfl_xor_sync(0x0000FFFFu, zp, o);
        if (tid == 0) s_invZ = 1.f / zp;
    }
    __syncthreads();

    // write normalized weights
    const float invZ = s_invZ;
    float4* gw4 = reinterpret_cast<float4*>(g_w) + (size_t)b * (Dd / 4);
    const float4* sc4 = reinterpret_cast<const float4*>(sc);
    #pragma unroll
    for (int it = 0; it < Dd / 4 / NTB; ++it) {  // 2 iters
        float4 wv = sc4[it * NTB + tid];
        wv.x *= invZ; wv.y *= invZ; wv.z *= invZ; wv.w *= invZ;
        gw4[it * NTB + tid] = wv;
    }
}

// ---------------- K3: weighted sum, one CTA per (b,l) ----------------
__global__ void __launch_bounds__(256) wsum_kernel(const float* __restrict__ x)
{
    __shared__ float red[8];
    const int l = blockIdx.x;
    const int b = blockIdx.y;
    const int tid = threadIdx.x;
    const int lane = tid & 31, wid = tid >> 5;

    const float4* __restrict__ xr4 =
        reinterpret_cast<const float4*>(x) + ((size_t)b * Ll + l) * (Dd / 4);
    const float4* __restrict__ wr4 =
        reinterpret_cast<const float4*>(g_w) + (size_t)b * (Dd / 4);

    float a0 = 0.f, a1 = 0.f, a2 = 0.f, a3 = 0.f;
    #pragma unroll
    for (int k = 0; k < 4; ++k) {
        const int i = k * 256 + tid;
        float4 wv = wr4[i];
        float4 xv = xr4[i];
        a0 = fmaf(wv.x, xv.x, a0);
        a1 = fmaf(wv.y, xv.y, a1);
        a2 = fmaf(wv.z, xv.z, a2);
        a3 = fmaf(wv.w, xv.w, a3);
    }
    float acc = (a0 + a1) + (a2 + a3);
    #pragma unroll
    for (int o = 16; o > 0; o >>= 1) acc += __shfl_xor_sync(0xFFFFFFFFu, acc, o);
    if (lane == 0) red[wid] = acc;
    __syncthreads();
    if (tid < 8) {
        acc = red[tid];
        #pragma unroll
        for (int o = 4; o > 0; o >>= 1) acc += __shfl_xor_sync(0x000000FFu, acc, o);
        if (tid == 0) g_y[(size_t)b * Ll + l] = acc;
    }
}

// ---------------- K4: head ----------------
__global__ void __launch_bounds__(128) head_kernel(
    const float* __restrict__ Wp, const float* __restrict__ bp,
    const float* __restrict__ gamma, const float* __restrict__ beta,
    const float* __restrict__ W1, const float* __restrict__ b1,
    const float* __restrict__ W2, const float* __restrict__ b2,
    float* __restrict__ out)
{
    __shared__ float yv[Ll];
    __shared__ float zs[Pp];
    __shared__ float as_[Hh];
    __shared__ float s_mu, s_rstd;
    const int b = blockIdx.x;
    const int tid = threadIdx.x;

    if (tid < Ll) yv[tid] = g_y[(size_t)b * Ll + tid];
    __syncthreads();
    if (tid < Pp) {
        float acc = bp[tid];
        #pragma unroll
        for (int l = 0; l < Ll; ++l) acc = fmaf(Wp[tid * Ll + l], yv[l], acc);
        zs[tid] = acc;
    }
    __syncthreads();
    if (tid < 32) {
        float a = zs[tid], bq = zs[tid + 32];
        float sum = a + bq;
        #pragma unroll
        for (int o = 16; o > 0; o >>= 1) sum += __shfl_xor_sync(0xFFFFFFFFu, sum, o);
        float mu = sum * (1.f / 64.f);
        float da = a - mu, db = bq - mu;
        float sq = da * da + db * db;
        #pragma unroll
        for (int o = 16; o > 0; o >>= 1) sq += __shfl_xor_sync(0xFFFFFFFFu, sq, o);
        if (tid == 0) { s_mu = mu; s_rstd = rsqrtf(sq * (1.f / 64.f) + 1e-5f); }
    }
    __syncthreads();
    if (tid < Pp) zs[tid] = (zs[tid] - s_mu) * s_rstd * gamma[tid] + beta[tid];
    __syncthreads();
    if (tid < Hh) {
        float acc = b1[tid];
        #pragma unroll
        for (int p = 0; p < Pp; ++p) acc = fmaf(W1[tid * Pp + p], zs[p], acc);
        as_[tid] = 0.5f * acc * (1.f + erff(acc * 0.70710678118654752f)); // exact GELU
    }
    __syncthreads();
    if (tid < 2) {
        float acc = b2[tid];
        #pragma unroll
        for (int h = 0; h < Hh; ++h) acc = fmaf(W2[tid * Hh + h], as_[h], acc);
        out[b * 2 + tid] = acc;
    }
}

extern "C" void kernel_launch(void* const* d_in, const int* in_sizes, int n_in,
                              void* d_out, int out_size) {
    const float* x     = (const float*)d_in[0];
    const float* Wp    = (const float*)d_in[1];
    const float* bp    = (const float*)d_in[2];
    const float* ws    = (const float*)d_in[3];
    const float* bsc   = (const float*)d_in[4];
    const float* gamma = (const float*)d_in[5];
    const float* beta  = (const float*)d_in[6];
    const float* W1    = (const float*)d_in[7];
    const float* b1    = (const float*)d_in[8];
    const float* W2    = (const float*)d_in[9];
    const float* b2    = (const float*)d_in[10];
    float* out = (float*)d_out;

    scores_kernel<<<Bb * 4, 256>>>(x, Wp, bp, ws, bsc);
    topk_w_kernel<<<Bb, NTB>>>();
    wsum_kernel<<<dim3(Ll, Bb), 256>>>(x);
    head_kernel<<<Bb, 128>>>(Wp, bp, gamma, beta, W1, b1, W2, b2, out);
}

// round 5
// speedup vs baseline: 1.1454x; 1.0169x over previous
#include <cuda_runtime.h>
#include <math.h>

// SparseDimAttention, GB300 sm_103a — 4-kernel pipeline.
// K1: scores[b,d] = sum_l v[l]*x[b,l,d] + c       (276 MB stream @ ~6.2 TB/s)
// K2: exact top-K via ONE 2048-bin radix pass + tie-rank cleanup -> w[b,d]
// K3: y[b,l] = sum_d w[b,d]*x[b,l,d]              (276 MB stream @ ~6.2 TB/s)
// K4: head, all weights prefetched to smem

constexpr int Ll = 33, Dd = 4096, Pp = 64, Kk = 512, Hh = 128, Bb = 512;

__device__ float g_scores[(size_t)Bb * Dd];
__device__ float g_w[(size_t)Bb * Dd];
__device__ float g_y[(size_t)Bb * Ll];

__device__ __forceinline__ unsigned int fkey(float f) {
    unsigned int u = __float_as_uint(f);
    return u ^ ((u & 0x80000000u) ? 0xFFFFFFFFu : 0x80000000u); // ascending monotonic
}

// ---------------- K1: scores ----------------
__global__ void __launch_bounds__(256) scores_kernel(
    const float* __restrict__ x, const float* __restrict__ Wp,
    const float* __restrict__ bp, const float* __restrict__ ws,
    const float* __restrict__ bsc)
{
    __shared__ float v[Ll];
    __shared__ float s_c;
    const int tid = threadIdx.x;
    if (tid < Ll) {
        float a = 0.f;
        #pragma unroll
        for (int p = 0; p < Pp; ++p) a = fmaf(ws[p], Wp[p * Ll + tid], a);
        v[tid] = a;
    } else if (tid == Ll) {
        float a = bsc[0];
        #pragma unroll
        for (int p = 0; p < Pp; ++p) a = fmaf(ws[p], bp[p], a);
        s_c = a;
    }
    __syncthreads();

    const int b  = blockIdx.x >> 2;
    const int d4 = ((blockIdx.x & 3) << 8) + tid;
    const float4* __restrict__ xb4 =
        reinterpret_cast<const float4*>(x) + (size_t)b * Ll * (Dd / 4) + d4;
    const float c = s_c;
    float4 acc = make_float4(c, c, c, c);
    #pragma unroll
    for (int l = 0; l < Ll; ++l) {
        float4 xv = xb4[(size_t)l * (Dd / 4)];
        const float vl = v[l];
        acc.x = fmaf(vl, xv.x, acc.x);
        acc.y = fmaf(vl, xv.y, acc.y);
        acc.z = fmaf(vl, xv.z, acc.z);
        acc.w = fmaf(vl, xv.w, acc.w);
    }
    reinterpret_cast<float4*>(g_scores)[(size_t)b * (Dd / 4) + d4] = acc;
}

// ---------------- K2: single-pass radix top-K + softmax -> w ----------------
#define NT2 256
constexpr int CH2 = Dd / NT2;    // 16
constexpr int BINS = 2048;       // top 11 bits of key
constexpr int BPT  = BINS / NT2; // 8 bins per thread

__global__ void __launch_bounds__(NT2) topk_w_kernel()
{
    __shared__ float sc[Dd];        // 16 KB: scores -> unnormalized weights
    __shared__ int   hist[BINS];    // 8 KB: counts -> suffix sums -> tie index list
    __shared__ float redf[8];
    __shared__ int   wsum_[8];
    __shared__ float s_m, s_invZ;
    __shared__ int   s_thr, s_rem, s_cnt, s_T;

    const int b = blockIdx.x, tid = threadIdx.x;
    const int lane = tid & 31, wid = tid >> 5;

    // load scores + running max; zero hist
    float m = -INFINITY;
    {
        const float4* gs4 = reinterpret_cast<const float4*>(g_scores) + (size_t)b * (Dd / 4);
        float4* sc4 = reinterpret_cast<float4*>(sc);
        #pragma unroll
        for (int it = 0; it < Dd / 4 / NT2; ++it) { // 4
            float4 v4 = gs4[it * NT2 + tid];
            sc4[it * NT2 + tid] = v4;
            m = fmaxf(fmaxf(m, fmaxf(v4.x, v4.y)), fmaxf(v4.z, v4.w));
        }
    }
    #pragma unroll
    for (int j = 0; j < BPT; ++j) hist[j * NT2 + tid] = 0;
    if (tid == 0) s_cnt = 0;
    #pragma unroll
    for (int o = 16; o > 0; o >>= 1) m = fmaxf(m, __shfl_xor_sync(0xFFFFFFFFu, m, o));
    if (lane == 0) redf[wid] = m;
    __syncthreads();
    if (tid < 8) {
        m = redf[tid];
        #pragma unroll
        for (int o = 4; o > 0; o >>= 1) m = fmaxf(m, __shfl_xor_sync(0x000000FFu, m, o));
        if (tid == 0) s_m = m;
    }

    // histogram on top-11-bit keys
    #pragma unroll
    for (int it = 0; it < CH2; ++it) {
        unsigned int k = fkey(sc[it * NT2 + tid]) >> 21;
        atomicAdd(&hist[k], 1);
    }
    __syncthreads();

    // suffix scan: hist[i] = #elements with bin >= i
    {
        const int base = tid * BPT;
        int c[BPT];
        #pragma unroll
        for (int j = 0; j < BPT; ++j) c[j] = hist[base + j];
        #pragma unroll
        for (int j = BPT - 2; j >= 0; --j) c[j] += c[j + 1];
        int tot = c[0];
        int inc = tot;
        #pragma unroll
        for (int o = 1; o < 32; o <<= 1) {
            int t = __shfl_up_sync(0xFFFFFFFFu, inc, o);
            if (lane >= o) inc += t;
        }
        if (lane == 31) wsum_[wid] = inc;
        __syncthreads();
        if (tid < 8) {
            int w = wsum_[tid];
            int iw = w;
            #pragma unroll
            for (int o = 1; o < 8; o <<= 1) {
                int t = __shfl_up_sync(0x000000FFu, iw, o);
                if (tid >= o) iw += t;
            }
            wsum_[tid] = iw - w;          // exclusive warp offset
            if (tid == 7) s_T = iw;       // grand total (= Dd)
        }
        __syncthreads();
        const int incl = wsum_[wid] + inc;   // inclusive prefix over threads <= tid
        const int S = s_T - incl;            // suffix over threads > tid
        #pragma unroll
        for (int j = 0; j < BPT; ++j) hist[base + j] = S + c[j];
    }
    __syncthreads();

    // threshold bin: hist[i] >= K && hist[i+1] < K
    #pragma unroll
    for (int j = 0; j < BPT; ++j) {
        const int i = tid * BPT + j;
        const int hv = hist[i];
        const int nx = (i < BINS - 1) ? hist[i + 1] : 0;
        if (hv >= Kk && nx < Kk) { s_thr = i; s_rem = Kk - nx; }
    }
    __syncthreads();

    const int thr = s_thr, rem = s_rem;
    const float mm = s_m;

    // build tie list (reuse hist as index list)
    #pragma unroll
    for (int it = 0; it < CH2; ++it) {
        const int d = it * NT2 + tid;
        if ((int)(fkey(sc[d]) >> 21) == thr) {
            int pos = atomicAdd(&s_cnt, 1);
            if (pos < BINS) hist[pos] = d;
        }
    }
    __syncthreads();
    const int cnt = s_cnt;
    const bool fast = (cnt <= BINS);

    // -------- READ-ONLY phase: snapshot owner scores + rank ties --------
    float sv[CH2];
    #pragma unroll
    for (int it = 0; it < CH2; ++it) sv[it] = sc[it * NT2 + tid];

    float twl[8]; int tdl[8];
    float twf[CH2];
    if (fast) {
        #pragma unroll
        for (int rep = 0; rep < 8; ++rep) {
            const int i = rep * NT2 + tid;
            twl[rep] = 0.f; tdl[rep] = -1;
            if (i < cnt) {
                const int d = hist[i];
                const float s = sc[d];
                const unsigned int ke = fkey(s);
                int rank = 0;
                for (int j2 = 0; j2 < cnt; ++j2) {
                    const int d2 = hist[j2];
                    const unsigned int k2 = fkey(sc[d2]);
                    rank += (k2 > ke) || (k2 == ke && d2 < d);
                }
                tdl[rep] = d;
                twl[rep] = (rank < rem) ? expf(s - mm) : 0.f;
            }
        }
    } else { // exact fallback (adversarial data only)
        #pragma unroll
        for (int it = 0; it < CH2; ++it) {
            const int d = it * NT2 + tid;
            const unsigned int ke = fkey(sv[it]);
            twf[it] = 0.f;
            if ((int)(ke >> 21) == thr) {
                int rank = 0;
                for (int d2 = 0; d2 < Dd; ++d2) {
                    const unsigned int k2 = fkey(sc[d2]);
                    if ((int)(k2 >> 21) == thr)
                        rank += (k2 > ke) || (k2 == ke && d2 < d);
                }
                twf[it] = (rank < rem) ? expf(sv[it] - mm) : 0.f;
            }
        }
    }
    __syncthreads();   // all reads of sc complete before any writes

    // -------- WRITE phase: disjoint writers --------
    float zp = 0.f;
    #pragma unroll
    for (int it = 0; it < CH2; ++it) {
        const int d = it * NT2 + tid;
        const int k11 = (int)(fkey(sv[it]) >> 21);
        if (k11 != thr) {
            const float w = (k11 > thr) ? expf(sv[it] - mm) : 0.f;
            sc[d] = w; zp += w;
        } else if (!fast) {
            sc[d] = twf[it]; zp += twf[it];
        }
        // fast-path tie slots written below by their tie-thread only
    }
    if (fast) {
        #pragma unroll
        for (int rep = 0; rep < 8; ++rep)
            if (tdl[rep] >= 0) { sc[tdl[rep]] = twl[rep]; zp += twl[rep]; }
    }
    #pragma unroll
    for (int o = 16; o > 0; o >>= 1) zp += __shfl_xor_sync(0xFFFFFFFFu, zp, o);
    if (lane == 0) redf[wid] = zp;
    __syncthreads();
    if (tid < 8) {
        zp = redf[tid];
        #pragma unroll
        for (int o = 4; o > 0; o >>= 1) zp += __shfl_xor_sync(0x000000FFu, zp, o);
        if (tid == 0) s_invZ = 1.f / zp;
    }
    __syncthreads();

    // normalized weights out
    const float invZ = s_invZ;
    float4* gw4 = reinterpret_cast<float4*>(g_w) + (size_t)b * (Dd / 4);
    const float4* sc4r = reinterpret_cast<const float4*>(sc);
    #pragma unroll
    for (int it = 0; it < Dd / 4 / NT2; ++it) {
        float4 wv = sc4r[it * NT2 + tid];
        wv.x *= invZ; wv.y *= invZ; wv.z *= invZ; wv.w *= invZ;
        gw4[it * NT2 + tid] = wv;
    }
}

// ---------------- K3: weighted sum, one CTA per (b,l) ----------------
__global__ void __launch_bounds__(256) wsum_kernel(const float* __restrict__ x)
{
    __shared__ float red[8];
    const int l = blockIdx.x;
    const int b = blockIdx.y;
    const int tid = threadIdx.x;
    const int lane = tid & 31, wid = tid >> 5;

    const float4* __restrict__ xr4 =
        reinterpret_cast<const float4*>(x) + ((size_t)b * Ll + l) * (Dd / 4);
    const float4* __restrict__ wr4 =
        reinterpret_cast<const float4*>(g_w) + (size_t)b * (Dd / 4);

    float a0 = 0.f, a1 = 0.f, a2 = 0.f, a3 = 0.f;
    #pragma unroll
    for (int k = 0; k < 4; ++k) {
        const int i = k * 256 + tid;
        float4 wv = wr4[i];
        float4 xv = xr4[i];
        a0 = fmaf(wv.x, xv.x, a0);
        a1 = fmaf(wv.y, xv.y, a1);
        a2 = fmaf(wv.z, xv.z, a2);
        a3 = fmaf(wv.w, xv.w, a3);
    }
    float acc = (a0 + a1) + (a2 + a3);
    #pragma unroll
    for (int o = 16; o > 0; o >>= 1) acc += __shfl_xor_sync(0xFFFFFFFFu, acc, o);
    if (lane == 0) red[wid] = acc;
    __syncthreads();
    if (tid < 8) {
        acc = red[tid];
        #pragma unroll
        for (int o = 4; o > 0; o >>= 1) acc += __shfl_xor_sync(0x000000FFu, acc, o);
        if (tid == 0) g_y[(size_t)b * Ll + l] = acc;
    }
}

// ---------------- K4: head (weights prefetched to smem) ----------------
__global__ void __launch_bounds__(256) head_kernel(
    const float* __restrict__ Wp, const float* __restrict__ bp,
    const float* __restrict__ gamma, const float* __restrict__ beta,
    const float* __restrict__ W1, const float* __restrict__ b1,
    const float* __restrict__ W2, const float* __restrict__ b2,
    float* __restrict__ out)
{
    __shared__ float sWp[Pp * Ll];   // 8448 B
    __shared__ float sW1[Hh * Pp];   // 32 KB
    __shared__ float sW2[2 * Hh];    // 1 KB
    __shared__ float yv[Ll];
    __shared__ float zs[Pp];
    __shared__ float as_[Hh];
    __shared__ float s_mu, s_rstd;
    const int b = blockIdx.x;
    const int tid = threadIdx.x;
    const int lane = tid & 31, wid = tid >> 5;

    if (tid < Ll) yv[tid] = g_y[(size_t)b * Ll + tid];     // FIX: was unreachable in R4
    for (int i = tid; i < Pp * Ll; i += 256) sWp[i] = Wp[i];
    for (int i = tid; i < Hh * Pp; i += 256) sW1[i] = W1[i];
    if (tid < 2 * Hh) sW2[tid] = W2[tid];
    __syncthreads();

    if (tid < Pp) {
        float acc = bp[tid];
        #pragma unroll
        for (int l = 0; l < Ll; ++l) acc = fmaf(sWp[tid * Ll + l], yv[l], acc);
        zs[tid] = acc;
    }
    __syncthreads();
    if (tid < 32) {
        float a = zs[tid], bq = zs[tid + 32];
        float sum = a + bq;
        #pragma unroll
        for (int o = 16; o > 0; o >>= 1) sum += __shfl_xor_sync(0xFFFFFFFFu, sum, o);
        float mu = sum * (1.f / 64.f);
        float da = a - mu, db = bq - mu;
        float sq = da * da + db * db;
        #pragma unroll
        for (int o = 16; o > 0; o >>= 1) sq += __shfl_xor_sync(0xFFFFFFFFu, sq, o);
        if (tid == 0) { s_mu = mu; s_rstd = rsqrtf(sq * (1.f / 64.f) + 1e-5f); }
    }
    __syncthreads();
    if (tid < Pp) zs[tid] = (zs[tid] - s_mu) * s_rstd * gamma[tid] + beta[tid];
    __syncthreads();
    if (tid < Hh) {
        float acc = b1[tid];
        #pragma unroll
        for (int p = 0; p < Pp; ++p) acc = fmaf(sW1[tid * Pp + p], zs[p], acc);
        as_[tid] = 0.5f * acc * (1.f + erff(acc * 0.70710678118654752f)); // exact GELU
    }
    __syncthreads();
    if (wid < 2) {  // two output neurons, one warp each
        float acc = 0.f;
        #pragma unroll
        for (int k = 0; k < 4; ++k) {
            const int h = k * 32 + lane;
            acc = fmaf(sW2[wid * Hh + h], as_[h], acc);
        }
        #pragma unroll
        for (int o = 16; o > 0; o >>= 1) acc += __shfl_xor_sync(0xFFFFFFFFu, acc, o);
        if (lane == 0) out[b * 2 + wid] = acc + b2[wid];
    }
}

extern "C" void kernel_launch(void* const* d_in, const int* in_sizes, int n_in,
                              void* d_out, int out_size) {
    const float* x     = (const float*)d_in[0];
    const float* Wp    = (const float*)d_in[1];
    const float* bp    = (const float*)d_in[2];
    const float* ws    = (const float*)d_in[3];
    const float* bsc   = (const float*)d_in[4];
    const float* gamma = (const float*)d_in[5];
    const float* beta  = (const float*)d_in[6];
    const float* W1    = (const float*)d_in[7];
    const float* b1    = (const float*)d_in[8];
    const float* W2    = (const float*)d_in[9];
    const float* b2    = (const float*)d_in[10];
    float* out = (float*)d_out;

    scores_kernel<<<Bb * 4, 256>>>(x, Wp, bp, ws, bsc);
    topk_w_kernel<<<Bb, NT2>>>();
    wsum_kernel<<<dim3(Ll, Bb), 256>>>(x);
    head_kernel<<<Bb, 256>>>(Wp, bp, gamma, beta, W1, b1, W2, b2, out);
}

// round 6
// speedup vs baseline: 1.2421x; 1.0844x over previous
#include <cuda_runtime.h>
#include <math.h>

// SparseDimAttention, GB300 sm_103a — 3-kernel pipeline.
// F1: scores[b,:] in smem (stream 276 MB) + exact top-K (linear-bin select) + softmax -> g_w
// K3: y[b,l] = sum_d w[b,d]*x[b,l,d]   (276 MB stream)
// K4: head, warp-per-batch, weights in smem

constexpr int Ll = 33, Dd = 4096, Pp = 64, Kk = 512, Hh = 128, Bb = 512;
constexpr int BINS = 2048;

__device__ float g_w[(size_t)Bb * Dd];
__device__ float g_y[(size_t)Bb * Ll];

__device__ __forceinline__ unsigned int fkey(float f) {
    unsigned int u = __float_as_uint(f);
    return u ^ ((u & 0x80000000u) ? 0xFFFFFFFFu : 0x80000000u); // ascending monotonic
}

// ---------------- F1: scores + top-K + softmax ----------------
#define NT1 256
constexpr int CH1 = Dd / NT1;     // 16
constexpr int BPT = BINS / NT1;   // 8

__global__ void __launch_bounds__(NT1) fused_kernel(
    const float* __restrict__ x, const float* __restrict__ Wp,
    const float* __restrict__ bp, const float* __restrict__ ws,
    const float* __restrict__ bsc)
{
    __shared__ float sc[Dd];        // 16 KB scores -> weights
    __shared__ int   hist[BINS];    // 8 KB counts -> suffix sums -> tie index list
    __shared__ float v[Ll];
    __shared__ float redmx[8], redmn[8], redf[8];
    __shared__ int   wsum_[8];
    __shared__ float s_c, s_m, s_lo, s_scale, s_invZ;
    __shared__ int   s_thr, s_rem, s_cnt, s_T;

    const int b = blockIdx.x, tid = threadIdx.x;
    const int lane = tid & 31, wid = tid >> 5;

    // fold projection: v[l] = sum_p ws[p]*Wp[p,l]; c = ws@bp + bs
    if (tid < Ll) {
        float a = 0.f;
        #pragma unroll
        for (int p = 0; p < Pp; ++p) a = fmaf(ws[p], Wp[p * Ll + tid], a);
        v[tid] = a;
    } else if (tid == Ll) {
        float a = bsc[0];
        #pragma unroll
        for (int p = 0; p < Pp; ++p) a = fmaf(ws[p], bp[p], a);
        s_c = a;
    }
    #pragma unroll
    for (int j = 0; j < BPT; ++j) hist[j * NT1 + tid] = 0;
    if (tid == 0) s_cnt = 0;
    __syncthreads();

    // stream x[b]: per-thread 4 float4 column groups
    float4 acc[4];
    {
        const float cc = s_c;
        #pragma unroll
        for (int g = 0; g < 4; ++g) acc[g] = make_float4(cc, cc, cc, cc);
        const float4* __restrict__ xb4 =
            reinterpret_cast<const float4*>(x) + (size_t)b * Ll * (Dd / 4);
        #pragma unroll
        for (int l = 0; l < Ll; ++l) {
            const float vl = v[l];
            const float4* row = xb4 + (size_t)l * (Dd / 4);
            #pragma unroll
            for (int g = 0; g < 4; ++g) {
                float4 xv = row[g * NT1 + tid];
                acc[g].x = fmaf(vl, xv.x, acc[g].x);
                acc[g].y = fmaf(vl, xv.y, acc[g].y);
                acc[g].z = fmaf(vl, xv.z, acc[g].z);
                acc[g].w = fmaf(vl, xv.w, acc[g].w);
            }
        }
        float4* sc4 = reinterpret_cast<float4*>(sc);
        float mx = -INFINITY, mn = INFINITY;
        #pragma unroll
        for (int g = 0; g < 4; ++g) {
            sc4[g * NT1 + tid] = acc[g];
            mx = fmaxf(mx, fmaxf(fmaxf(acc[g].x, acc[g].y), fmaxf(acc[g].z, acc[g].w)));
            mn = fminf(mn, fminf(fminf(acc[g].x, acc[g].y), fminf(acc[g].z, acc[g].w)));
        }
        #pragma unroll
        for (int o = 16; o > 0; o >>= 1) {
            mx = fmaxf(mx, __shfl_xor_sync(0xFFFFFFFFu, mx, o));
            mn = fminf(mn, __shfl_xor_sync(0xFFFFFFFFu, mn, o));
        }
        if (lane == 0) { redmx[wid] = mx; redmn[wid] = mn; }
    }
    __syncthreads();
    if (tid < 8) {
        float mx = redmx[tid], mn = redmn[tid];
        #pragma unroll
        for (int o = 4; o > 0; o >>= 1) {
            mx = fmaxf(mx, __shfl_xor_sync(0x000000FFu, mx, o));
            mn = fminf(mn, __shfl_xor_sync(0x000000FFu, mn, o));
        }
        if (tid == 0) {
            s_m = mx; s_lo = mn;
            const float r = mx - mn;
            s_scale = (r > 0.f) ? ((float)(BINS - 1) / r) : 0.f;
        }
    }
    __syncthreads();

    const float lo = s_lo, scale = s_scale, mm = s_m;
    // value-uniform histogram
    #pragma unroll
    for (int it = 0; it < CH1; ++it) {
        const float s = sc[it * NT1 + tid];
        int bin = (int)((s - lo) * scale);
        bin = min(BINS - 1, max(0, bin));
        atomicAdd(&hist[bin], 1);
    }
    __syncthreads();

    // suffix scan: hist[i] = #elements with bin >= i
    {
        const int base = tid * BPT;
        int c[BPT];
        #pragma unroll
        for (int j = 0; j < BPT; ++j) c[j] = hist[base + j];
        #pragma unroll
        for (int j = BPT - 2; j >= 0; --j) c[j] += c[j + 1];
        int inc = c[0];
        #pragma unroll
        for (int o = 1; o < 32; o <<= 1) {
            int t = __shfl_up_sync(0xFFFFFFFFu, inc, o);
            if (lane >= o) inc += t;
        }
        if (lane == 31) wsum_[wid] = inc;
        __syncthreads();
        if (tid < 8) {
            int w = wsum_[tid];
            int iw = w;
            #pragma unroll
            for (int o = 1; o < 8; o <<= 1) {
                int t = __shfl_up_sync(0x000000FFu, iw, o);
                if (tid >= o) iw += t;
            }
            wsum_[tid] = iw - w;
            if (tid == 7) s_T = iw;
        }
        __syncthreads();
        const int S = s_T - (wsum_[wid] + inc);
        #pragma unroll
        for (int j = 0; j < BPT; ++j) hist[base + j] = S + c[j];
    }
    __syncthreads();

    // threshold bin
    #pragma unroll
    for (int j = 0; j < BPT; ++j) {
        const int i = tid * BPT + j;
        const int hv = hist[i];
        const int nx = (i < BINS - 1) ? hist[i + 1] : 0;
        if (hv >= Kk && nx < Kk) { s_thr = i; s_rem = Kk - nx; }
    }
    __syncthreads();
    const int thr = s_thr, rem = s_rem;

    // tie list (reuse hist)
    #pragma unroll
    for (int it = 0; it < CH1; ++it) {
        const int d = it * NT1 + tid;
        int bin = (int)((sc[d] - lo) * scale);
        bin = min(BINS - 1, max(0, bin));
        if (bin == thr) {
            int pos = atomicAdd(&s_cnt, 1);
            if (pos < BINS) hist[pos] = d;
        }
    }
    __syncthreads();
    const int cnt = s_cnt;
    const bool fast = (cnt <= BINS);

    // READ-ONLY: snapshot owner scores + rank ties by (key desc, idx asc)
    float sv[CH1];
    #pragma unroll
    for (int it = 0; it < CH1; ++it) sv[it] = sc[it * NT1 + tid];

    float twl[8]; int tdl[8];
    float twf[CH1];
    if (fast) {
        #pragma unroll
        for (int rep = 0; rep < 8; ++rep) {
            const int i = rep * NT1 + tid;
            twl[rep] = 0.f; tdl[rep] = -1;
            if (i < cnt) {
                const int d = hist[i];
                const float s = sc[d];
                const unsigned int ke = fkey(s);
                int rank = 0;
                for (int j2 = 0; j2 < cnt; ++j2) {
                    const int d2 = hist[j2];
                    const unsigned int k2 = fkey(sc[d2]);
                    rank += (k2 > ke) || (k2 == ke && d2 < d);
                }
                tdl[rep] = d;
                twl[rep] = (rank < rem) ? expf(s - mm) : 0.f;
            }
        }
    } else { // exact fallback (degenerate data only)
        #pragma unroll
        for (int it = 0; it < CH1; ++it) {
            const int d = it * NT1 + tid;
            int bin = (int)((sv[it] - lo) * scale);
            bin = min(BINS - 1, max(0, bin));
            twf[it] = 0.f;
            if (bin == thr) {
                const unsigned int ke = fkey(sv[it]);
                int rank = 0;
                for (int d2 = 0; d2 < Dd; ++d2) {
                    const float s2 = sc[d2];
                    int b2i = (int)((s2 - lo) * scale);
                    b2i = min(BINS - 1, max(0, b2i));
                    if (b2i == thr) {
                        const unsigned int k2 = fkey(s2);
                        rank += (k2 > ke) || (k2 == ke && d2 < d);
                    }
                }
                twf[it] = (rank < rem) ? expf(sv[it] - mm) : 0.f;
            }
        }
    }
    __syncthreads();   // all sc reads done before writes

    // WRITE: disjoint writers
    float zp = 0.f;
    #pragma unroll
    for (int it = 0; it < CH1; ++it) {
        const int d = it * NT1 + tid;
        int bin = (int)((sv[it] - lo) * scale);
        bin = min(BINS - 1, max(0, bin));
        if (bin != thr) {
            const float w = (bin > thr) ? expf(sv[it] - mm) : 0.f;
            sc[d] = w; zp += w;
        } else if (!fast) {
            sc[d] = twf[it]; zp += twf[it];
        }
    }
    if (fast) {
        #pragma unroll
        for (int rep = 0; rep < 8; ++rep)
            if (tdl[rep] >= 0) { sc[tdl[rep]] = twl[rep]; zp += twl[rep]; }
    }
    #pragma unroll
    for (int o = 16; o > 0; o >>= 1) zp += __shfl_xor_sync(0xFFFFFFFFu, zp, o);
    if (lane == 0) redf[wid] = zp;
    __syncthreads();
    if (tid < 8) {
        zp = redf[tid];
        #pragma unroll
        for (int o = 4; o > 0; o >>= 1) zp += __shfl_xor_sync(0x000000FFu, zp, o);
        if (tid == 0) s_invZ = 1.f / zp;
    }
    __syncthreads();

    // normalized weights out
    const float invZ = s_invZ;
    float4* gw4 = reinterpret_cast<float4*>(g_w) + (size_t)b * (Dd / 4);
    const float4* sc4r = reinterpret_cast<const float4*>(sc);
    #pragma unroll
    for (int g = 0; g < 4; ++g) {
        float4 wv = sc4r[g * NT1 + tid];
        wv.x *= invZ; wv.y *= invZ; wv.z *= invZ; wv.w *= invZ;
        gw4[g * NT1 + tid] = wv;
    }
}

// ---------------- K3: weighted sum, one CTA per (b,l) ----------------
__global__ void __launch_bounds__(256) wsum_kernel(const float* __restrict__ x)
{
    __shared__ float red[8];
    const int l = blockIdx.x;
    const int b = blockIdx.y;
    const int tid = threadIdx.x;
    const int lane = tid & 31, wid = tid >> 5;

    const float4* __restrict__ xr4 =
        reinterpret_cast<const float4*>(x) + ((size_t)b * Ll + l) * (Dd / 4);
    const float4* __restrict__ wr4 =
        reinterpret_cast<const float4*>(g_w) + (size_t)b * (Dd / 4);

    float a0 = 0.f, a1 = 0.f, a2 = 0.f, a3 = 0.f;
    #pragma unroll
    for (int k = 0; k < 4; ++k) {
        const int i = k * 256 + tid;
        float4 wv = wr4[i];
        float4 xv = xr4[i];
        a0 = fmaf(wv.x, xv.x, a0);
        a1 = fmaf(wv.y, xv.y, a1);
        a2 = fmaf(wv.z, xv.z, a2);
        a3 = fmaf(wv.w, xv.w, a3);
    }
    float acc = (a0 + a1) + (a2 + a3);
    #pragma unroll
    for (int o = 16; o > 0; o >>= 1) acc += __shfl_xor_sync(0xFFFFFFFFu, acc, o);
    if (lane == 0) red[wid] = acc;
    __syncthreads();
    if (tid < 8) {
        acc = red[tid];
        #pragma unroll
        for (int o = 4; o > 0; o >>= 1) acc += __shfl_xor_sync(0x000000FFu, acc, o);
        if (tid == 0) g_y[(size_t)b * Ll + l] = acc;
    }
}

// ---------------- K4: head, warp-per-batch (8 batches/CTA) ----------------
__global__ void __launch_bounds__(256) head_kernel(
    const float* __restrict__ Wp, const float* __restrict__ bp,
    const float* __restrict__ gamma, const float* __restrict__ beta,
    const float* __restrict__ W1, const float* __restrict__ b1,
    const float* __restrict__ W2, const float* __restrict__ b2,
    float* __restrict__ out)
{
    __shared__ float sWp[Pp * Ll];    // 8448 B
    __shared__ float sW1[Hh * Pp];    // 32 KB
    __shared__ float sW2[2 * Hh];     // 1 KB
    __shared__ float sbp[Pp], sg[Pp], sbe[Pp], sb1[Hh], sb2[2];
    __shared__ float yw[8][Ll + 1];   // +1 pad
    __shared__ float zw[8][Pp];
    const int tid = threadIdx.x;
    const int lane = tid & 31, wid = tid >> 5;

    for (int i = tid; i < Pp * Ll; i += 256) sWp[i] = Wp[i];
    for (int i = tid; i < Hh * Pp; i += 256) sW1[i] = W1[i];
    if (tid < 2 * Hh) sW2[tid] = W2[tid];
    if (tid < Pp) { sbp[tid] = bp[tid]; sg[tid] = gamma[tid]; sbe[tid] = beta[tid]; }
    if (tid < Hh) sb1[tid] = b1[tid];
    if (tid < 2) sb2[tid] = b2[tid];

    const int b = blockIdx.x * 8 + wid;
    for (int i = lane; i < Ll; i += 32) yw[wid][i] = g_y[(size_t)b * Ll + i];
    __syncthreads();

    // z = Wp@y + bp  (2 outputs per lane; 33 is odd -> bank-conflict-free)
    float z0 = sbp[lane], z1 = sbp[lane + 32];
    #pragma unroll
    for (int l = 0; l < Ll; ++l) {
        const float y = yw[wid][l];
        z0 = fmaf(sWp[lane * Ll + l], y, z0);
        z1 = fmaf(sWp[(lane + 32) * Ll + l], y, z1);
    }
    // LayerNorm over 64 via warp reduce
    float sum = z0 + z1;
    #pragma unroll
    for (int o = 16; o > 0; o >>= 1) sum += __shfl_xor_sync(0xFFFFFFFFu, sum, o);
    const float mu = sum * (1.f / 64.f);
    const float d0 = z0 - mu, d1 = z1 - mu;
    float sq = d0 * d0 + d1 * d1;
    #pragma unroll
    for (int o = 16; o > 0; o >>= 1) sq += __shfl_xor_sync(0xFFFFFFFFu, sq, o);
    const float rstd = rsqrtf(sq * (1.f / 64.f) + 1e-5f);
    zw[wid][lane]      = d0 * rstd * sg[lane] + sbe[lane];
    zw[wid][lane + 32] = d1 * rstd * sg[lane + 32] + sbe[lane + 32];
    __syncwarp();

    // W1 + exact GELU: 4 h per lane (rotated p index -> conflict-free)
    float a[4];
    #pragma unroll
    for (int k = 0; k < 4; ++k) {
        const int j = k * 32 + lane;
        float acc = sb1[j];
        #pragma unroll
        for (int p = 0; p < Pp; ++p) {
            const int pr = (p + lane) & (Pp - 1);
            acc = fmaf(sW1[j * Pp + pr], zw[wid][pr], acc);
        }
        a[k] = 0.5f * acc * (1.f + erff(acc * 0.70710678118654752f));
    }
    // W2
    float o0 = 0.f, o1 = 0.f;
    #pragma unroll
    for (int k = 0; k < 4; ++k) {
        const int j = k * 32 + lane;
        o0 = fmaf(sW2[j], a[k], o0);
        o1 = fmaf(sW2[Hh + j], a[k], o1);
    }
    #pragma unroll
    for (int o = 16; o > 0; o >>= 1) {
        o0 += __shfl_xor_sync(0xFFFFFFFFu, o0, o);
        o1 += __shfl_xor_sync(0xFFFFFFFFu, o1, o);
    }
    if (lane == 0) {
        out[b * 2 + 0] = o0 + sb2[0];
        out[b * 2 + 1] = o1 + sb2[1];
    }
}

extern "C" void kernel_launch(void* const* d_in, const int* in_sizes, int n_in,
                              void* d_out, int out_size) {
    const float* x     = (const float*)d_in[0];
    const float* Wp    = (const float*)d_in[1];
    const float* bp    = (const float*)d_in[2];
    const float* ws    = (const float*)d_in[3];
    const float* bsc   = (const float*)d_in[4];
    const float* gamma = (const float*)d_in[5];
    const float* beta  = (const float*)d_in[6];
    const float* W1    = (const float*)d_in[7];
    const float* b1    = (const float*)d_in[8];
    const float* W2    = (const float*)d_in[9];
    const float* b2    = (const float*)d_in[10];
    float* out = (float*)d_out;

    fused_kernel<<<Bb, NT1>>>(x, Wp, bp, ws, bsc);
    wsum_kernel<<<dim3(Ll, Bb), 256>>>(x);
    head_kernel<<<Bb / 8, 256>>>(Wp, bp, gamma, beta, W1, b1, W2, b2, out);
}

// round 7
// speedup vs baseline: 1.4180x; 1.1416x over previous
#include <cuda_runtime.h>
#include <math.h>

// SparseDimAttention, GB300 sm_103a — 3-kernel pipeline.
// F1: scores[b,:] in smem (stream 276 MB) + exact top-K (linear-bin select) + softmax -> g_w
//     launch_bounds(256,4): whole 512-CTA grid resident in one wave.
// K3: y[b,l] = sum_d w[b,d]*x[b,l,d]   (276 MB stream @ ~5.9 TB/s)
// K4: head, warp-per-batch, weights in smem

constexpr int Ll = 33, Dd = 4096, Pp = 64, Kk = 512, Hh = 128, Bb = 512;
constexpr int BINS = 1024;

__device__ float g_w[(size_t)Bb * Dd];
__device__ float g_y[(size_t)Bb * Ll];

__device__ __forceinline__ unsigned int fkey(float f) {
    unsigned int u = __float_as_uint(f);
    return u ^ ((u & 0x80000000u) ? 0xFFFFFFFFu : 0x80000000u); // ascending monotonic
}

// ---------------- F1: scores + top-K + softmax ----------------
#define NT1 256
constexpr int CH1 = Dd / NT1;     // 16
constexpr int BPT = BINS / NT1;   // 4
constexpr int TREP = BINS / NT1;  // 4 tie reps

__global__ void __launch_bounds__(NT1, 4) fused_kernel(
    const float* __restrict__ x, const float* __restrict__ Wp,
    const float* __restrict__ bp, const float* __restrict__ ws,
    const float* __restrict__ bsc)
{
    __shared__ float sc[Dd];        // 16 KB scores -> weights
    __shared__ int   hist[BINS];    // 4 KB counts -> suffix sums -> tie index list
    __shared__ float v[Ll];
    __shared__ float redmx[8], redmn[8], redf[8];
    __shared__ int   wsum_[8];
    __shared__ float s_c, s_m, s_lo, s_scale, s_invZ;
    __shared__ int   s_thr, s_rem, s_cnt, s_T;

    const int b = blockIdx.x, tid = threadIdx.x;
    const int lane = tid & 31, wid = tid >> 5;

    // fold projection: v[l] = sum_p ws[p]*Wp[p,l]; c = ws@bp + bs
    if (tid < Ll) {
        float a = 0.f;
        #pragma unroll
        for (int p = 0; p < Pp; ++p) a = fmaf(ws[p], Wp[p * Ll + tid], a);
        v[tid] = a;
    } else if (tid == Ll) {
        float a = bsc[0];
        #pragma unroll
        for (int p = 0; p < Pp; ++p) a = fmaf(ws[p], bp[p], a);
        s_c = a;
    }
    #pragma unroll
    for (int j = 0; j < BPT; ++j) hist[j * NT1 + tid] = 0;
    if (tid == 0) s_cnt = 0;
    __syncthreads();

    // stream x[b]: per-thread 4 float4 column groups
    float4 acc[4];
    {
        const float cc = s_c;
        #pragma unroll
        for (int g = 0; g < 4; ++g) acc[g] = make_float4(cc, cc, cc, cc);
        const float4* __restrict__ xb4 =
            reinterpret_cast<const float4*>(x) + (size_t)b * Ll * (Dd / 4);
        #pragma unroll 3
        for (int l = 0; l < Ll; ++l) {
            const float vl = v[l];
            const float4* row = xb4 + (size_t)l * (Dd / 4);
            #pragma unroll
            for (int g = 0; g < 4; ++g) {
                float4 xv = row[g * NT1 + tid];
                acc[g].x = fmaf(vl, xv.x, acc[g].x);
                acc[g].y = fmaf(vl, xv.y, acc[g].y);
                acc[g].z = fmaf(vl, xv.z, acc[g].z);
                acc[g].w = fmaf(vl, xv.w, acc[g].w);
            }
        }
        float4* sc4 = reinterpret_cast<float4*>(sc);
        float mx = -INFINITY, mn = INFINITY;
        #pragma unroll
        for (int g = 0; g < 4; ++g) {
            sc4[g * NT1 + tid] = acc[g];
            mx = fmaxf(mx, fmaxf(fmaxf(acc[g].x, acc[g].y), fmaxf(acc[g].z, acc[g].w)));
            mn = fminf(mn, fminf(fminf(acc[g].x, acc[g].y), fminf(acc[g].z, acc[g].w)));
        }
        #pragma unroll
        for (int o = 16; o > 0; o >>= 1) {
            mx = fmaxf(mx, __shfl_xor_sync(0xFFFFFFFFu, mx, o));
            mn = fminf(mn, __shfl_xor_sync(0xFFFFFFFFu, mn, o));
        }
        if (lane == 0) { redmx[wid] = mx; redmn[wid] = mn; }
    }
    __syncthreads();
    if (tid < 8) {
        float mx = redmx[tid], mn = redmn[tid];
        #pragma unroll
        for (int o = 4; o > 0; o >>= 1) {
            mx = fmaxf(mx, __shfl_xor_sync(0x000000FFu, mx, o));
            mn = fminf(mn, __shfl_xor_sync(0x000000FFu, mn, o));
        }
        if (tid == 0) {
            s_m = mx; s_lo = mn;
            const float r = mx - mn;
            s_scale = (r > 0.f) ? ((float)(BINS - 1) / r) : 0.f;
        }
    }
    __syncthreads();

    const float lo = s_lo, scale = s_scale, mm = s_m;
    // value-uniform histogram
    #pragma unroll
    for (int it = 0; it < CH1; ++it) {
        const float s = sc[it * NT1 + tid];
        int bin = (int)((s - lo) * scale);
        bin = min(BINS - 1, max(0, bin));
        atomicAdd(&hist[bin], 1);
    }
    __syncthreads();

    // suffix scan: hist[i] = #elements with bin >= i
    {
        const int base = tid * BPT;
        int c[BPT];
        #pragma unroll
        for (int j = 0; j < BPT; ++j) c[j] = hist[base + j];
        #pragma unroll
        for (int j = BPT - 2; j >= 0; --j) c[j] += c[j + 1];
        int inc = c[0];
        #pragma unroll
        for (int o = 1; o < 32; o <<= 1) {
            int t = __shfl_up_sync(0xFFFFFFFFu, inc, o);
            if (lane >= o) inc += t;
        }
        if (lane == 31) wsum_[wid] = inc;
        __syncthreads();
        if (tid < 8) {
            int w = wsum_[tid];
            int iw = w;
            #pragma unroll
            for (int o = 1; o < 8; o <<= 1) {
                int t = __shfl_up_sync(0x000000FFu, iw, o);
                if (tid >= o) iw += t;
            }
            wsum_[tid] = iw - w;
            if (tid == 7) s_T = iw;
        }
        __syncthreads();
        const int S = s_T - (wsum_[wid] + inc);
        #pragma unroll
        for (int j = 0; j < BPT; ++j) hist[base + j] = S + c[j];
    }
    __syncthreads();

    // threshold bin
    #pragma unroll
    for (int j = 0; j < BPT; ++j) {
        const int i = tid * BPT + j;
        const int hv = hist[i];
        const int nx = (i < BINS - 1) ? hist[i + 1] : 0;
        if (hv >= Kk && nx < Kk) { s_thr = i; s_rem = Kk - nx; }
    }
    __syncthreads();
    const int thr = s_thr, rem = s_rem;

    // tie list (reuse hist)
    #pragma unroll
    for (int it = 0; it < CH1; ++it) {
        const int d = it * NT1 + tid;
        int bin = (int)((sc[d] - lo) * scale);
        bin = min(BINS - 1, max(0, bin));
        if (bin == thr) {
            int pos = atomicAdd(&s_cnt, 1);
            if (pos < BINS) hist[pos] = d;
        }
    }
    __syncthreads();
    const int cnt = s_cnt;
    const bool fast = (cnt <= BINS);

    // READ-ONLY: snapshot owner scores + rank ties by (key desc, idx asc)
    float sv[CH1];
    #pragma unroll
    for (int it = 0; it < CH1; ++it) sv[it] = sc[it * NT1 + tid];

    float twl[TREP]; int tdl[TREP];
    float twf[CH1];
    if (fast) {
        #pragma unroll
        for (int rep = 0; rep < TREP; ++rep) {
            const int i = rep * NT1 + tid;
            twl[rep] = 0.f; tdl[rep] = -1;
            if (i < cnt) {
                const int d = hist[i];
                const float s = sc[d];
                const unsigned int ke = fkey(s);
                int rank = 0;
                for (int j2 = 0; j2 < cnt; ++j2) {
                    const int d2 = hist[j2];
                    const unsigned int k2 = fkey(sc[d2]);
                    rank += (k2 > ke) || (k2 == ke && d2 < d);
                }
                tdl[rep] = d;
                twl[rep] = (rank < rem) ? expf(s - mm) : 0.f;
            }
        }
    } else { // exact fallback (degenerate data only)
        #pragma unroll
        for (int it = 0; it < CH1; ++it) {
            const int d = it * NT1 + tid;
            int bin = (int)((sv[it] - lo) * scale);
            bin = min(BINS - 1, max(0, bin));
            twf[it] = 0.f;
            if (bin == thr) {
                const unsigned int ke = fkey(sv[it]);
                int rank = 0;
                for (int d2 = 0; d2 < Dd; ++d2) {
                    const float s2 = sc[d2];
                    int b2i = (int)((s2 - lo) * scale);
                    b2i = min(BINS - 1, max(0, b2i));
                    if (b2i == thr) {
                        const unsigned int k2 = fkey(s2);
                        rank += (k2 > ke) || (k2 == ke && d2 < d);
                    }
                }
                twf[it] = (rank < rem) ? expf(sv[it] - mm) : 0.f;
            }
        }
    }
    __syncthreads();   // all sc reads done before writes

    // WRITE: disjoint writers
    float zp = 0.f;
    #pragma unroll
    for (int it = 0; it < CH1; ++it) {
        const int d = it * NT1 + tid;
        int bin = (int)((sv[it] - lo) * scale);
        bin = min(BINS - 1, max(0, bin));
        if (bin != thr) {
            const float w = (bin > thr) ? expf(sv[it] - mm) : 0.f;
            sc[d] = w; zp += w;
        } else if (!fast) {
            sc[d] = twf[it]; zp += twf[it];
        }
    }
    if (fast) {
        #pragma unroll
        for (int rep = 0; rep < TREP; ++rep)
            if (tdl[rep] >= 0) { sc[tdl[rep]] = twl[rep]; zp += twl[rep]; }
    }
    #pragma unroll
    for (int o = 16; o > 0; o >>= 1) zp += __shfl_xor_sync(0xFFFFFFFFu, zp, o);
    if (lane == 0) redf[wid] = zp;
    __syncthreads();
    if (tid < 8) {
        zp = redf[tid];
        #pragma unroll
        for (int o = 4; o > 0; o >>= 1) zp += __shfl_xor_sync(0x000000FFu, zp, o);
        if (tid == 0) s_invZ = 1.f / zp;
    }
    __syncthreads();

    // normalized weights out
    const float invZ = s_invZ;
    float4* gw4 = reinterpret_cast<float4*>(g_w) + (size_t)b * (Dd / 4);
    const float4* sc4r = reinterpret_cast<const float4*>(sc);
    #pragma unroll
    for (int g = 0; g < 4; ++g) {
        float4 wv = sc4r[g * NT1 + tid];
        wv.x *= invZ; wv.y *= invZ; wv.z *= invZ; wv.w *= invZ;
        gw4[g * NT1 + tid] = wv;
    }
}

// ---------------- K3: weighted sum, one CTA per (b,l) ----------------
__global__ void __launch_bounds__(256) wsum_kernel(const float* __restrict__ x)
{
    __shared__ float red[8];
    const int l = blockIdx.x;
    const int b = blockIdx.y;
    const int tid = threadIdx.x;
    const int lane = tid & 31, wid = tid >> 5;

    const float4* __restrict__ xr4 =
        reinterpret_cast<const float4*>(x) + ((size_t)b * Ll + l) * (Dd / 4);
    const float4* __restrict__ wr4 =
        reinterpret_cast<const float4*>(g_w) + (size_t)b * (Dd / 4);

    float a0 = 0.f, a1 = 0.f, a2 = 0.f, a3 = 0.f;
    #pragma unroll
    for (int k = 0; k < 4; ++k) {
        const int i = k * 256 + tid;
        float4 wv = wr4[i];
        float4 xv = xr4[i];
        a0 = fmaf(wv.x, xv.x, a0);
        a1 = fmaf(wv.y, xv.y, a1);
        a2 = fmaf(wv.z, xv.z, a2);
        a3 = fmaf(wv.w, xv.w, a3);
    }
    float acc = (a0 + a1) + (a2 + a3);
    #pragma unroll
    for (int o = 16; o > 0; o >>= 1) acc += __shfl_xor_sync(0xFFFFFFFFu, acc, o);
    if (lane == 0) red[wid] = acc;
    __syncthreads();
    if (tid < 8) {
        acc = red[tid];
        #pragma unroll
        for (int o = 4; o > 0; o >>= 1) acc += __shfl_xor_sync(0x000000FFu, acc, o);
        if (tid == 0) g_y[(size_t)b * Ll + l] = acc;
    }
}

// ---------------- K4: head, warp-per-batch (8 batches/CTA) ----------------
__global__ void __launch_bounds__(256) head_kernel(
    const float* __restrict__ Wp, const float* __restrict__ bp,
    const float* __restrict__ gamma, const float* __restrict__ beta,
    const float* __restrict__ W1, const float* __restrict__ b1,
    const float* __restrict__ W2, const float* __restrict__ b2,
    float* __restrict__ out)
{
    __shared__ float sWp[Pp * Ll];    // 8448 B
    __shared__ float sW1[Hh * Pp];    // 32 KB
    __shared__ float sW2[2 * Hh];     // 1 KB
    __shared__ float sbp[Pp], sg[Pp], sbe[Pp], sb1[Hh], sb2[2];
    __shared__ float yw[8][Ll + 1];   // +1 pad
    __shared__ float zw[8][Pp];
    const int tid = threadIdx.x;
    const int lane = tid & 31, wid = tid >> 5;

    for (int i = tid; i < Pp * Ll; i += 256) sWp[i] = Wp[i];
    for (int i = tid; i < Hh * Pp; i += 256) sW1[i] = W1[i];
    if (tid < 2 * Hh) sW2[tid] = W2[tid];
    if (tid < Pp) { sbp[tid] = bp[tid]; sg[tid] = gamma[tid]; sbe[tid] = beta[tid]; }
    if (tid < Hh) sb1[tid] = b1[tid];
    if (tid < 2) sb2[tid] = b2[tid];

    const int b = blockIdx.x * 8 + wid;
    for (int i = lane; i < Ll; i += 32) yw[wid][i] = g_y[(size_t)b * Ll + i];
    __syncthreads();

    // z = Wp@y + bp  (2 outputs per lane; 33 is odd -> bank-conflict-free)
    float z0 = sbp[lane], z1 = sbp[lane + 32];
    #pragma unroll
    for (int l = 0; l < Ll; ++l) {
        const float y = yw[wid][l];
        z0 = fmaf(sWp[lane * Ll + l], y, z0);
        z1 = fmaf(sWp[(lane + 32) * Ll + l], y, z1);
    }
    // LayerNorm over 64 via warp reduce
    float sum = z0 + z1;
    #pragma unroll
    for (int o = 16; o > 0; o >>= 1) sum += __shfl_xor_sync(0xFFFFFFFFu, sum, o);
    const float mu = sum * (1.f / 64.f);
    const float d0 = z0 - mu, d1 = z1 - mu;
    float sq = d0 * d0 + d1 * d1;
    #pragma unroll
    for (int o = 16; o > 0; o >>= 1) sq += __shfl_xor_sync(0xFFFFFFFFu, sq, o);
    const float rstd = rsqrtf(sq * (1.f / 64.f) + 1e-5f);
    zw[wid][lane]      = d0 * rstd * sg[lane] + sbe[lane];
    zw[wid][lane + 32] = d1 * rstd * sg[lane + 32] + sbe[lane + 32];
    __syncwarp();

    // W1 + exact GELU: 4 h per lane (rotated p index -> conflict-free)
    float a[4];
    #pragma unroll
    for (int k = 0; k < 4; ++k) {
        const int j = k * 32 + lane;
        float acc = sb1[j];
        #pragma unroll
        for (int p = 0; p < Pp; ++p) {
            const int pr = (p + lane) & (Pp - 1);
            acc = fmaf(sW1[j * Pp + pr], zw[wid][pr], acc);
        }
        a[k] = 0.5f * acc * (1.f + erff(acc * 0.70710678118654752f));
    }
    // W2
    float o0 = 0.f, o1 = 0.f;
    #pragma unroll
    for (int k = 0; k < 4; ++k) {
        const int j = k * 32 + lane;
        o0 = fmaf(sW2[j], a[k], o0);
        o1 = fmaf(sW2[Hh + j], a[k], o1);
    }
    #pragma unroll
    for (int o = 16; o > 0; o >>= 1) {
        o0 += __shfl_xor_sync(0xFFFFFFFFu, o0, o);
        o1 += __shfl_xor_sync(0xFFFFFFFFu, o1, o);
    }
    if (lane == 0) {
        out[b * 2 + 0] = o0 + sb2[0];
        out[b * 2 + 1] = o1 + sb2[1];
    }
}

extern "C" void kernel_launch(void* const* d_in, const int* in_sizes, int n_in,
                              void* d_out, int out_size) {
    const float* x     = (const float*)d_in[0];
    const float* Wp    = (const float*)d_in[1];
    const float* bp    = (const float*)d_in[2];
    const float* ws    = (const float*)d_in[3];
    const float* bsc   = (const float*)d_in[4];
    const float* gamma = (const float*)d_in[5];
    const float* beta  = (const float*)d_in[6];
    const float* W1    = (const float*)d_in[7];
    const float* b1    = (const float*)d_in[8];
    const float* W2    = (const float*)d_in[9];
    const float* b2    = (const float*)d_in[10];
    float* out = (float*)d_out;

    fused_kernel<<<Bb, NT1>>>(x, Wp, bp, ws, bsc);
    wsum_kernel<<<dim3(Ll, Bb), 256>>>(x);
    head_kernel<<<Bb / 8, 256>>>(Wp, bp, gamma, beta, W1, b1, W2, b2, out);
}